// round 15
// baseline (speedup 1.0000x reference)
#include <cuda_runtime.h>
#include <cuda_fp16.h>
#include <math.h>
#include <stdint.h>

// Problem dims (fixed by the reference)
#define B_ 8
#define T_ 2048
#define C_ 1024
#define F_ 4096
#define M_ (B_ * T_)   // 16384 rows

constexpr size_t S_  = (size_t)M_ * C_;   // 16,777,216
constexpr size_t SF_ = (size_t)M_ * F_;   // 67,108,864
constexpr size_t CC_ = (size_t)C_ * C_;
constexpr size_t FC_ = (size_t)F_ * C_;

#define NCH 16            // WKV chunks
#define CHL (T_ / NCH)    // 128 steps per chunk
#define NCHAN (B_ * C_)   // 8192 channels

// ---------------------------------------------------------------------------
// Scratch (static device globals — allocation-free per harness rules)
// ---------------------------------------------------------------------------
__device__ __half g_xk[S_];
__device__ __half g_xv[S_];
__device__ __half g_xr[S_];
__device__ float  g_ek[S_];     // exp(k)  (from Wk GEMM epilogue)
__device__ float  g_v[S_];
__device__ float  g_r[S_];      // sigmoid(r)
__device__ __half g_ao[(size_t)M_ * 2048];  // [rwkv | x_half] along K
__device__ float  g_x2[S_];
__device__ __half g_gk[S_];
__device__ __half g_gr[S_];
__device__ __half g_kk[SF_];
// half weights
__device__ __half g_wkt[CC_];
__device__ __half g_wvt[CC_];
__device__ __half g_wrt[CC_];
__device__ __half g_wos[2 * CC_];  // [Wo | shortW] along K
__device__ __half g_fwrt[CC_];
__device__ __half g_fwkt[FC_];
__device__ __half g_fwvt[FC_];
// WKV chunk-scan state (a, b per chunk)
__device__ float g_sa[NCHAN * NCH], g_sb[NCHAN * NCH];
__device__ float g_pa[NCHAN * NCH], g_pb[NCHAN * NCH];

// ---------------------------------------------------------------------------
// helpers
// ---------------------------------------------------------------------------
__device__ __forceinline__ void cp_async16(void* smem, const void* gmem) {
    uint32_t s = (uint32_t)__cvta_generic_to_shared(smem);
    asm volatile("cp.async.cg.shared.global [%0], [%1], 16;" :: "r"(s), "l"(gmem));
}
#define CP_COMMIT() asm volatile("cp.async.commit_group;")
#define CP_WAIT0()  asm volatile("cp.async.wait_group 0;")
#define CP_WAIT1()  asm volatile("cp.async.wait_group 1;")

__device__ __forceinline__ void mma_f16(float* d, const uint32_t* a, const uint32_t* b) {
    asm volatile(
        "mma.sync.aligned.m16n8k16.row.col.f32.f16.f16.f32 "
        "{%0,%1,%2,%3}, {%4,%5,%6,%7}, {%8,%9}, {%0,%1,%2,%3};"
        : "+f"(d[0]), "+f"(d[1]), "+f"(d[2]), "+f"(d[3])
        : "r"(a[0]), "r"(a[1]), "r"(a[2]), "r"(a[3]),
          "r"(b[0]), "r"(b[1]));
}

__device__ __forceinline__ void ldsm_x4(uint32_t* r, uint32_t addr) {
    asm volatile("ldmatrix.sync.aligned.m8n8.x4.shared.b16 {%0,%1,%2,%3}, [%4];"
        : "=r"(r[0]), "=r"(r[1]), "=r"(r[2]), "=r"(r[3]) : "r"(addr));
}

__device__ __forceinline__ uint2 f4_to_h4(float4 v) {
    __half2 h0 = __floats2half2_rn(v.x, v.y);
    __half2 h1 = __floats2half2_rn(v.z, v.w);
    uint2 o;
    o.x = *(uint32_t*)&h0;
    o.y = *(uint32_t*)&h1;
    return o;
}

// ---------------------------------------------------------------------------
// Merged cvt kernels
// ---------------------------------------------------------------------------
__global__ void __launch_bounds__(256) cvt4C(const float* s0, const float* s1,
                                             const float* s2, const float* s3,
                                             __half* d0, __half* d1,
                                             __half* d2, __half* d3) {
    const int seg = blockIdx.x >> 10;
    const int i = ((blockIdx.x & 1023) << 8) + threadIdx.x;
    const float* src = (seg == 0) ? s0 : (seg == 1) ? s1 : (seg == 2) ? s2 : s3;
    __half* dst      = (seg == 0) ? d0 : (seg == 1) ? d1 : (seg == 2) ? d2 : d3;
    ((uint2*)dst)[i] = f4_to_h4(((const float4*)src)[i]);
}

__global__ void __launch_bounds__(256) cvt2F(const float* s0, const float* s1,
                                             __half* d0, __half* d1) {
    const int seg = blockIdx.x >> 12;
    const int i = ((blockIdx.x & 4095) << 8) + threadIdx.x;
    const float* src = (seg == 0) ? s0 : s1;
    __half* dst      = (seg == 0) ? d0 : d1;
    ((uint2*)dst)[i] = f4_to_h4(((const float4*)src)[i]);
}

// wos pair: 2 strided C*C segments into g_wos (row stride 2048 halfs)
__global__ void __launch_bounds__(256) cvt_wos(const float* s0, const float* s1,
                                               __half* dst) {
    const int seg = blockIdx.x >> 10;
    const int i4 = ((blockIdx.x & 1023) << 8) + threadIdx.x;
    const float* src = (seg == 0) ? s0 : s1;
    const int off = (seg == 0) ? 0 : 256;
    const int row = i4 >> 8;
    const int col = i4 & 255;
    ((uint2*)dst)[(size_t)row * 512 + off + col] = f4_to_h4(((const float4*)src)[i4]);
}

// ---------------------------------------------------------------------------
// Fused LayerNorm + time-shift-mix.
// NOUT=3 additionally writes the raw x row (half) into xout with row stride
// 2048 halfs at column offset 1024 (the [.. | x] half of g_ao).
// ---------------------------------------------------------------------------
#define ROWS_PB 32

template <int NOUT>
__global__ void __launch_bounds__(256) ln_mix_kernel(
        const float* __restrict__ x,
        const float* __restrict__ w, const float* __restrict__ b,
        const float* __restrict__ m0, const float* __restrict__ m1,
        const float* __restrict__ m2,
        __half* __restrict__ o0, __half* __restrict__ o1,
        __half* __restrict__ o2, __half* __restrict__ xout) {
    __shared__ float sm_s[8], sm_ss[8];
    const int tid = threadIdx.x;
    const int wid = tid >> 5, lid = tid & 31;
    const size_t row0 = (size_t)blockIdx.x * ROWS_PB;
    const bool at_t0 = ((row0 & (T_ - 1)) == 0);

    const float4 wv = ((const float4*)w)[tid];
    const float4 bv = ((const float4*)b)[tid];
    const float4 mk0 = ((const float4*)m0)[tid];
    const float4 mk1 = ((const float4*)m1)[tid];
    const float4 mk2 = (NOUT == 3) ? ((const float4*)m2)[tid]
                                   : make_float4(0.f, 0.f, 0.f, 0.f);

    float4 raw;   // raw x row of the most recent ln_row call
    auto ln_row = [&](size_t row) -> float4 {
        float4 xv4 = ((const float4*)(x + row * C_))[tid];
        raw = xv4;
        float s  = xv4.x + xv4.y + xv4.z + xv4.w;
        float ss = xv4.x * xv4.x + xv4.y * xv4.y + xv4.z * xv4.z + xv4.w * xv4.w;
        #pragma unroll
        for (int o = 16; o > 0; o >>= 1) {
            s  += __shfl_down_sync(0xffffffffu, s,  o);
            ss += __shfl_down_sync(0xffffffffu, ss, o);
        }
        __syncthreads();
        if (lid == 0) { sm_s[wid] = s; sm_ss[wid] = ss; }
        __syncthreads();
        float ts = 0.f, tss = 0.f;
        #pragma unroll
        for (int q = 0; q < 8; ++q) { ts += sm_s[q]; tss += sm_ss[q]; }
        const float mean = ts * (1.0f / C_);
        const float var  = tss * (1.0f / C_) - mean * mean;
        const float rstd = rsqrtf(var + 1e-5f);
        float4 r;
        r.x = (xv4.x - mean) * rstd * wv.x + bv.x;
        r.y = (xv4.y - mean) * rstd * wv.y + bv.y;
        r.z = (xv4.z - mean) * rstd * wv.z + bv.z;
        r.w = (xv4.w - mean) * rstd * wv.w + bv.w;
        return r;
    };

    float4 prev = make_float4(0.f, 0.f, 0.f, 0.f);
    if (!at_t0) prev = ln_row(row0 - 1);

    for (int i = 0; i < ROWS_PB; ++i) {
        const size_t row = row0 + i;
        float4 cur = ln_row(row);
        const size_t o4 = row * (C_ / 4) + tid;

        {
            float a0 = cur.x * mk0.x + prev.x * (1.f - mk0.x);
            float a1 = cur.y * mk0.y + prev.y * (1.f - mk0.y);
            float a2 = cur.z * mk0.z + prev.z * (1.f - mk0.z);
            float a3 = cur.w * mk0.w + prev.w * (1.f - mk0.w);
            ((uint2*)o0)[o4] = f4_to_h4(make_float4(a0, a1, a2, a3));
        }
        {
            float a0 = cur.x * mk1.x + prev.x * (1.f - mk1.x);
            float a1 = cur.y * mk1.y + prev.y * (1.f - mk1.y);
            float a2 = cur.z * mk1.z + prev.z * (1.f - mk1.z);
            float a3 = cur.w * mk1.w + prev.w * (1.f - mk1.w);
            ((uint2*)o1)[o4] = f4_to_h4(make_float4(a0, a1, a2, a3));
        }
        if (NOUT == 3) {
            float a0 = cur.x * mk2.x + prev.x * (1.f - mk2.x);
            float a1 = cur.y * mk2.y + prev.y * (1.f - mk2.y);
            float a2 = cur.z * mk2.z + prev.z * (1.f - mk2.z);
            float a3 = cur.w * mk2.w + prev.w * (1.f - mk2.w);
            ((uint2*)o2)[o4] = f4_to_h4(make_float4(a0, a1, a2, a3));
            // raw x -> ao right half (row stride 512 uint2, offset 256)
            ((uint2*)xout)[row * 512 + 256 + tid] = f4_to_h4(raw);
        }
        prev = cur;
    }
}

// ---------------------------------------------------------------------------
// WKV chunk-parallel scan, UNNORMALIZED form
// ---------------------------------------------------------------------------
__global__ void __launch_bounds__(256) wkv_part(const float* __restrict__ decay,
                                                const float* __restrict__ ek,
                                                const float* __restrict__ v) {
    int gid = blockIdx.x * blockDim.x + threadIdx.x;
    int j    = gid >> 13;
    int chan = gid & (NCHAN - 1);
    int b = chan >> 10;
    int c = chan & (C_ - 1);
    const float ew = __expf(-__expf(decay[c]));
    size_t off = ((size_t)b * T_ + (size_t)j * CHL) * C_ + c;

    float a = 0.f, bb = 0.f;
    #pragma unroll 4
    for (int t = 0; t < CHL; ++t, off += C_) {
        const float e = ek[off];
        const float vt = v[off];
        a  = fmaf(ew, a, e * vt);
        bb = fmaf(ew, bb, e);
    }
    g_sa[j * NCHAN + chan] = a;
    g_sb[j * NCHAN + chan] = bb;
}

__global__ void __launch_bounds__(256) wkv_scan(const float* __restrict__ decay) {
    int chan = blockIdx.x * blockDim.x + threadIdx.x;
    if (chan >= NCHAN) return;
    int c = chan & (C_ - 1);
    const float w = -__expf(decay[c]);
    const float dw = __expf((float)CHL * w);

    float a = 0.f, bb = 0.f;
    #pragma unroll
    for (int j = 0; j < NCH; ++j) {
        g_pa[j * NCHAN + chan] = a;
        g_pb[j * NCHAN + chan] = bb;
        a  = fmaf(a,  dw, g_sa[j * NCHAN + chan]);
        bb = fmaf(bb, dw, g_sb[j * NCHAN + chan]);
    }
}

__global__ void __launch_bounds__(256) wkv_out(const float* __restrict__ decay,
                                               const float* __restrict__ first,
                                               const float* __restrict__ ek,
                                               const float* __restrict__ v,
                                               const float* __restrict__ r,
                                               __half* __restrict__ out) {
    int gid = blockIdx.x * blockDim.x + threadIdx.x;
    int j    = gid >> 13;
    int chan = gid & (NCHAN - 1);
    int b = chan >> 10;
    int c = chan & (C_ - 1);
    const float ew = __expf(-__expf(decay[c]));
    const float eu = __expf(first[c]);
    size_t off  = ((size_t)b * T_ + (size_t)j * CHL) * C_ + c;
    size_t offo = ((size_t)b * T_ + (size_t)j * CHL) * 2048 + c;

    float a  = g_pa[j * NCHAN + chan];
    float bb = g_pb[j * NCHAN + chan];

    #pragma unroll 4
    for (int t = 0; t < CHL; ++t, off += C_, offo += 2048) {
        const float e  = ek[off];
        const float vt = v[off];
        const float x  = eu * e;
        const float y  = __fdividef(fmaf(x, vt, a), bb + x);
        out[offo] = __float2half_rn(y * r[off]);
        a  = fmaf(ew, a, e * vt);
        bb = fmaf(ew, bb, e);
    }
}

// ---------------------------------------------------------------------------
// fp16 tensor-core GEMM core (1818.7us config)
// ---------------------------------------------------------------------------
#define BM 128
#define BN 128
#define BK 32
#define BKPH 40
#define STG 3
#define STAGE_HALFS (128 * BKPH)
#define GEMM_SMEM (STG * STAGE_HALFS * 2 * 2)   // 61440 bytes

struct GemmCtx {
    uint32_t aBase, bBase;
    int lrow, lk;
    const __half* Ag;
    const __half* Wg;
    __half* AsBase;
    __half* BsBase;
};

__device__ __forceinline__ void gemm_main(GemmCtx& cx, float acc[4][4][4], int K) {
    auto load_stage = [&](int s, int k0) {
        __half* a = cx.AsBase + s * STAGE_HALFS + cx.lrow * BKPH + cx.lk;
        __half* b = cx.BsBase + s * STAGE_HALFS + cx.lrow * BKPH + cx.lk;
        cp_async16(a,     cx.Ag + k0);
        cp_async16(a + 8, cx.Ag + k0 + 8);
        cp_async16(b,     cx.Wg + k0);
        cp_async16(b + 8, cx.Wg + k0 + 8);
    };

    load_stage(0, 0); CP_COMMIT();
    load_stage(1, BK); CP_COMMIT();

    const int nk = K / BK;
    for (int it = 0; it < nk; ++it) {
        const int cur = it % 3;
        if (it == nk - 1) { CP_WAIT0(); } else { CP_WAIT1(); }
        __syncthreads();

        const uint32_t soff = (uint32_t)cur * (STAGE_HALFS * 2);

        // ---- ks = 0 fragments ----
        uint32_t af0[4][4], b00[4], b01[4];
        ldsm_x4(b00, cx.bBase + soff);
        ldsm_x4(b01, cx.bBase + soff + 16 * BKPH * 2);
        #pragma unroll
        for (int mt = 0; mt < 4; ++mt)
            ldsm_x4(af0[mt], cx.aBase + soff + (uint32_t)mt * (16 * BKPH * 2));

        if (it + 2 < nk) {
            load_stage((it + 2) % 3, (it + 2) * BK);
            CP_COMMIT();
        }

        #pragma unroll
        for (int mt = 0; mt < 4; ++mt) {
            mma_f16(acc[mt][0], af0[mt], b00);
            mma_f16(acc[mt][1], af0[mt], b00 + 2);
            mma_f16(acc[mt][2], af0[mt], b01);
            mma_f16(acc[mt][3], af0[mt], b01 + 2);
        }

        // ---- ks = 1 ----
        uint32_t af1[4][4], b10[4], b11[4];
        ldsm_x4(b10, cx.bBase + soff + 32);
        ldsm_x4(b11, cx.bBase + soff + 32 + 16 * BKPH * 2);
        #pragma unroll
        for (int mt = 0; mt < 4; ++mt)
            ldsm_x4(af1[mt], cx.aBase + soff + 32 + (uint32_t)mt * (16 * BKPH * 2));
        #pragma unroll
        for (int mt = 0; mt < 4; ++mt) {
            mma_f16(acc[mt][0], af1[mt], b10);
            mma_f16(acc[mt][1], af1[mt], b10 + 2);
            mma_f16(acc[mt][2], af1[mt], b11);
            mma_f16(acc[mt][3], af1[mt], b11 + 2);
        }
    }
}

__device__ __forceinline__ void gemm_setup(GemmCtx& cx, const __half* A,
                                           const __half* W, int K,
                                           __half* smh) {
    const int tid  = threadIdx.x;
    const int wid  = tid >> 5;
    const int lane = tid & 31;
    cx.AsBase = smh;
    cx.BsBase = smh + STG * STAGE_HALFS;
    cx.lrow = tid >> 1;
    cx.lk   = (tid & 1) * 16;
    cx.Ag = A + ((size_t)blockIdx.y * BM + cx.lrow) * (size_t)K + cx.lk;
    cx.Wg = W + ((size_t)blockIdx.x * BN + cx.lrow) * (size_t)K + cx.lk;
    const int warp_m = wid >> 2;
    const int warp_n = wid & 3;
    const uint32_t smA = (uint32_t)__cvta_generic_to_shared(cx.AsBase);
    const uint32_t smB = (uint32_t)__cvta_generic_to_shared(cx.BsBase);
    cx.aBase = smA +
        (((uint32_t)(warp_m * 64 + (lane & 15)) * BKPH + (uint32_t)(lane >> 4) * 8) << 1);
    cx.bBase = smB +
        (((uint32_t)(warp_n * 32 + ((lane >> 4) << 3) + (lane & 7)) * BKPH +
          (uint32_t)((lane >> 3) & 1) * 8) << 1);
}

#define ZERO_ACC(acc)                                                          \
    _Pragma("unroll")                                                          \
    for (int i = 0; i < 4; ++i)                                                \
        _Pragma("unroll")                                                      \
        for (int j = 0; j < 4; ++j)                                            \
            _Pragma("unroll")                                                  \
            for (int r = 0; r < 4; ++r) acc[i][j][r] = 0.f;

#define EPI_LOOP(BODY)                                                         \
    const int tid  = threadIdx.x;                                              \
    const int wid  = tid >> 5;                                                 \
    const int lane = tid & 31;                                                 \
    const int g    = lane >> 2;                                                \
    const int tig  = lane & 3;                                                 \
    const int warp_m = wid >> 2;                                               \
    const int warp_n = wid & 3;                                                \
    _Pragma("unroll")                                                          \
    for (int mt = 0; mt < 4; ++mt) {                                           \
        const int r0 = (int)(blockIdx.y * BM) + warp_m * 64 + mt * 16 + g;     \
        _Pragma("unroll")                                                      \
        for (int nt = 0; nt < 4; ++nt) {                                       \
            const int c0 = (int)(blockIdx.x * BN) + warp_n * 32 + nt * 8 + 2 * tig; \
            _Pragma("unroll")                                                  \
            for (int hi = 0; hi < 2; ++hi) {                                   \
                const int row = r0 + hi * 8;                                   \
                const size_t off = (size_t)row * N + c0;                       \
                float v0 = acc[mt][nt][hi * 2 + 0];                            \
                float v1 = acc[mt][nt][hi * 2 + 1];                            \
                BODY                                                           \
            }                                                                  \
        }                                                                      \
    }

// Single GEMM, MODE: 0 store f32, 2 relu^2->half
template <int MODE>
__global__ void __launch_bounds__(256, 2) gemm_tc(const __half* __restrict__ A,
                                                  const __half* __restrict__ W,
                                                  void* __restrict__ Cc,
                                                  int N, int K) {
    extern __shared__ __half smh[];
    GemmCtx cx;
    gemm_setup(cx, A, W, K, smh);
    float acc[4][4][4];
    ZERO_ACC(acc)
    gemm_main(cx, acc, K);

    EPI_LOOP({
        if (MODE == 2) {
            v0 = fmaxf(v0, 0.f); v0 = v0 * v0;
            v1 = fmaxf(v1, 0.f); v1 = v1 * v1;
            __half2 hv = __floats2half2_rn(v0, v1);
            *(__half2*)((__half*)Cc + off) = hv;
        } else {
            float2 o; o.x = v0; o.y = v1;
            *(float2*)((float*)Cc + off) = o;
        }
    })
}

// Batched TimeMix triple GEMM: z=0 exp(k), z=1 v, z=2 sigmoid(r)
__global__ void __launch_bounds__(256, 2) gemm_tc3(
        const __half* __restrict__ A0, const __half* __restrict__ A1,
        const __half* __restrict__ A2,
        const __half* __restrict__ W0, const __half* __restrict__ W1,
        const __half* __restrict__ W2,
        float* __restrict__ C0, float* __restrict__ C1,
        float* __restrict__ C2, int N, int K) {
    extern __shared__ __half smh[];
    const int z = blockIdx.z;
    const __half* A = (z == 0) ? A0 : (z == 1) ? A1 : A2;
    const __half* W = (z == 0) ? W0 : (z == 1) ? W1 : W2;
    float* Cc       = (z == 0) ? C0 : (z == 1) ? C1 : C2;

    GemmCtx cx;
    gemm_setup(cx, A, W, K, smh);
    float acc[4][4][4];
    ZERO_ACC(acc)
    gemm_main(cx, acc, K);

    EPI_LOOP({
        if (z == 0) {
            v0 = __expf(v0); v1 = __expf(v1);
        } else if (z == 2) {
            v0 = 1.f / (1.f + __expf(-v0));
            v1 = 1.f / (1.f + __expf(-v1));
        }
        float2 o; o.x = v0; o.y = v1;
        *(float2*)(Cc + off) = o;
    })
}

// Fused FFN tail: acc_r = gr@fWr^T (K=1024) -> sigmoid -> packed half;
// acc_kv = kk@fWv^T (K=4096); out = x2 + sigmoid_r * kv.
__global__ void __launch_bounds__(256, 2) gemm_fuse(
        const __half* __restrict__ Ar, const __half* __restrict__ Wr_,
        const __half* __restrict__ Akv, const __half* __restrict__ Wkv,
        const float* __restrict__ x2, float* __restrict__ out) {
    extern __shared__ __half smh[];
    float acc[4][4][4];

    {
        GemmCtx cx;
        gemm_setup(cx, Ar, Wr_, C_, smh);
        ZERO_ACC(acc)
        gemm_main(cx, acc, C_);
    }

    uint32_t rpack[4][4][2];
    #pragma unroll
    for (int mt = 0; mt < 4; ++mt)
        #pragma unroll
        for (int nt = 0; nt < 4; ++nt) {
            float s0 = 1.f / (1.f + __expf(-acc[mt][nt][0]));
            float s1 = 1.f / (1.f + __expf(-acc[mt][nt][1]));
            float s2 = 1.f / (1.f + __expf(-acc[mt][nt][2]));
            float s3 = 1.f / (1.f + __expf(-acc[mt][nt][3]));
            __half2 p0 = __floats2half2_rn(s0, s1);
            __half2 p1 = __floats2half2_rn(s2, s3);
            rpack[mt][nt][0] = *(uint32_t*)&p0;
            rpack[mt][nt][1] = *(uint32_t*)&p1;
        }

    __syncthreads();

    {
        GemmCtx cx;
        gemm_setup(cx, Akv, Wkv, F_, smh);
        ZERO_ACC(acc)
        gemm_main(cx, acc, F_);
    }

    const int N = C_;
    EPI_LOOP({
        float2 a1 = *(const float2*)(x2 + off);
        __half2 hp = *(__half2*)&rpack[mt][nt][hi];
        float2 rr = __half22float2(hp);
        v0 = a1.x + rr.x * v0;
        v1 = a1.y + rr.y * v1;
        float2 o; o.x = v0; o.y = v1;
        *(float2*)(out + off) = o;
    })
}

// ---------------------------------------------------------------------------
// Launch
// ---------------------------------------------------------------------------
template <typename T>
static T* sym(const void* s) {
    void* p = nullptr;
    cudaGetSymbolAddress(&p, s);
    return (T*)p;
}

extern "C" void kernel_launch(void* const* d_in, const int* in_sizes, int n_in,
                              void* d_out, int out_size) {
    const float* x        = (const float*)d_in[0];
    const float* ln1_w    = (const float*)d_in[1];
    const float* ln1_b    = (const float*)d_in[2];
    const float* ln2_w    = (const float*)d_in[3];
    const float* ln2_b    = (const float*)d_in[4];
    const float* t_decay  = (const float*)d_in[5];
    const float* t_first  = (const float*)d_in[6];
    const float* mix_k    = (const float*)d_in[7];
    const float* mix_v    = (const float*)d_in[8];
    const float* mix_r    = (const float*)d_in[9];
    const float* Wk       = (const float*)d_in[10];
    const float* Wv       = (const float*)d_in[11];
    const float* Wr       = (const float*)d_in[12];
    const float* Wo       = (const float*)d_in[13];
    const float* fmix_k   = (const float*)d_in[14];
    const float* fmix_r   = (const float*)d_in[15];
    const float* fWk      = (const float*)d_in[16];   // [F, C]
    const float* fWr      = (const float*)d_in[17];   // [C, C]
    const float* fWv      = (const float*)d_in[18];   // [C, F]
    const float* shortW   = (const float*)d_in[19];
    float* out = (float*)d_out;

    __half* xk   = sym<__half>(g_xk);
    __half* xv   = sym<__half>(g_xv);
    __half* xr   = sym<__half>(g_xr);
    float*  ekb  = sym<float>(g_ek);
    float*  vbuf = sym<float>(g_v);
    float*  rbuf = sym<float>(g_r);
    __half* ao   = sym<__half>(g_ao);
    float*  x2   = sym<float>(g_x2);
    __half* gk   = sym<__half>(g_gk);
    __half* gr   = sym<__half>(g_gr);
    __half* kkb  = sym<__half>(g_kk);
    __half* wkt  = sym<__half>(g_wkt);
    __half* wvt  = sym<__half>(g_wvt);
    __half* wrt  = sym<__half>(g_wrt);
    __half* wos  = sym<__half>(g_wos);
    __half* fwrt = sym<__half>(g_fwrt);
    __half* fwkt = sym<__half>(g_fwkt);
    __half* fwvt = sym<__half>(g_fwvt);

    cudaFuncSetAttribute(gemm_tc<0>, cudaFuncAttributeMaxDynamicSharedMemorySize, GEMM_SMEM);
    cudaFuncSetAttribute(gemm_tc<2>, cudaFuncAttributeMaxDynamicSharedMemorySize, GEMM_SMEM);
    cudaFuncSetAttribute(gemm_tc3, cudaFuncAttributeMaxDynamicSharedMemorySize, GEMM_SMEM);
    cudaFuncSetAttribute(gemm_fuse, cudaFuncAttributeMaxDynamicSharedMemorySize, GEMM_SMEM);

    const dim3 blk(256);
    const dim3 grid_gC(C_ / BN, M_ / BM);        // (8, 128)
    const dim3 grid_gC3(C_ / BN, M_ / BM, 3);    // batched triple
    const dim3 grid_gF(F_ / BN, M_ / BM);        // (32, 128)
    const dim3 grid_lnmix(M_ / ROWS_PB);         // 512

    // Launch order: gemm_tc3 is launch #4 so ncu's capture lands on it.
    // 1: merged C-weight cvt (wk, wv, wr, fWr)
    cvt4C<<<4096, blk>>>(Wk, Wv, Wr, fWr, wkt, wvt, wrt, fwrt);
    // 2: LN1 + mix (+ writes x->half into ao right half)
    ln_mix_kernel<3><<<grid_lnmix, blk>>>(x, ln1_w, ln1_b,
                                          mix_k, mix_v, mix_r, xk, xv, xr, ao);
    // 3: wos pair (Wo | shortW)
    cvt_wos<<<2048, blk>>>(Wo, shortW, wos);
    // 4: TimeMix triple GEMM  <-- ncu capture target
    gemm_tc3<<<grid_gC3, blk, GEMM_SMEM>>>(xk, xv, xr, wkt, wvt, wrt,
                                           ekb, vbuf, rbuf, C_, C_);
    // 5: merged F-weight cvt (fWk, fWv) — needed later only
    cvt2F<<<8192, blk>>>(fWk, fWv, fwkt, fwvt);
    wkv_part<<<(NCHAN * NCH) / 256, blk>>>(t_decay, ekb, vbuf);
    wkv_scan<<<NCHAN / 256, blk>>>(t_decay);
    wkv_out<<<(NCHAN * NCH) / 256, blk>>>(t_decay, t_first, ekb, vbuf, rbuf, ao);
    // x2 = [rwkv | x] @ [Wo | shortW]^T   (K = 2048)
    gemm_tc<0><<<grid_gC, blk, GEMM_SMEM>>>(ao, wos, x2, C_, 2048);

    // --- ChannelMix path ---
    ln_mix_kernel<2><<<grid_lnmix, blk>>>(x2, ln2_w, ln2_b,
                                          fmix_k, fmix_r, nullptr, gk, gr,
                                          nullptr, nullptr);
    gemm_tc<2><<<grid_gF, blk, GEMM_SMEM>>>(gk, fwkt, kkb, F_, C_);
    gemm_fuse<<<grid_gC, blk, GEMM_SMEM>>>(gr, fwrt, kkb, fwvt, x2, out);
}

// round 16
// speedup vs baseline: 1.0172x; 1.0172x over previous
#include <cuda_runtime.h>
#include <cuda_fp16.h>
#include <math.h>
#include <stdint.h>

// Problem dims (fixed by the reference)
#define B_ 8
#define T_ 2048
#define C_ 1024
#define F_ 4096
#define M_ (B_ * T_)   // 16384 rows

constexpr size_t S_  = (size_t)M_ * C_;   // 16,777,216
constexpr size_t SF_ = (size_t)M_ * F_;   // 67,108,864
constexpr size_t CC_ = (size_t)C_ * C_;
constexpr size_t FC_ = (size_t)F_ * C_;

#define NCH 16            // WKV chunks
#define CHL (T_ / NCH)    // 128 steps per chunk
#define NCHAN (B_ * C_)   // 8192 channels

// ---------------------------------------------------------------------------
// Scratch (static device globals — allocation-free per harness rules)
// ---------------------------------------------------------------------------
__device__ __half g_xk[S_];
__device__ __half g_xv[S_];
__device__ __half g_xr[S_];
__device__ float  g_ek[S_];     // exp(k)  (from Wk GEMM epilogue)
__device__ float  g_v[S_];
__device__ float  g_r[S_];      // sigmoid(r)
__device__ __half g_ao[(size_t)M_ * 2048];  // [rwkv | x_half] along K
__device__ float  g_x2[S_];
__device__ __half g_gk[S_];
__device__ __half g_gr[S_];
__device__ __half g_kk[SF_];
// half weights
__device__ __half g_wkt[CC_];
__device__ __half g_wvt[CC_];
__device__ __half g_wrt[CC_];
__device__ __half g_wos[2 * CC_];  // [Wo | shortW] along K
__device__ __half g_fwrt[CC_];
__device__ __half g_fwkt[FC_];
__device__ __half g_fwvt[FC_];
// WKV chunk-scan state (a, b per chunk)
__device__ float g_sa[NCHAN * NCH], g_sb[NCHAN * NCH];
__device__ float g_pa[NCHAN * NCH], g_pb[NCHAN * NCH];

// ---------------------------------------------------------------------------
// helpers
// ---------------------------------------------------------------------------
__device__ __forceinline__ void cp_async16(void* smem, const void* gmem) {
    uint32_t s = (uint32_t)__cvta_generic_to_shared(smem);
    asm volatile("cp.async.cg.shared.global [%0], [%1], 16;" :: "r"(s), "l"(gmem));
}
#define CP_COMMIT() asm volatile("cp.async.commit_group;")
#define CP_WAIT0()  asm volatile("cp.async.wait_group 0;")

__device__ __forceinline__ void mma_f16(float* d, const uint32_t* a, const uint32_t* b) {
    asm volatile(
        "mma.sync.aligned.m16n8k16.row.col.f32.f16.f16.f32 "
        "{%0,%1,%2,%3}, {%4,%5,%6,%7}, {%8,%9}, {%0,%1,%2,%3};"
        : "+f"(d[0]), "+f"(d[1]), "+f"(d[2]), "+f"(d[3])
        : "r"(a[0]), "r"(a[1]), "r"(a[2]), "r"(a[3]),
          "r"(b[0]), "r"(b[1]));
}

__device__ __forceinline__ void ldsm_x4(uint32_t* r, uint32_t addr) {
    asm volatile("ldmatrix.sync.aligned.m8n8.x4.shared.b16 {%0,%1,%2,%3}, [%4];"
        : "=r"(r[0]), "=r"(r[1]), "=r"(r[2]), "=r"(r[3]) : "r"(addr));
}

__device__ __forceinline__ uint2 f4_to_h4(float4 v) {
    __half2 h0 = __floats2half2_rn(v.x, v.y);
    __half2 h1 = __floats2half2_rn(v.z, v.w);
    uint2 o;
    o.x = *(uint32_t*)&h0;
    o.y = *(uint32_t*)&h1;
    return o;
}

// ---------------------------------------------------------------------------
// Merged cvt kernels
// ---------------------------------------------------------------------------
__global__ void __launch_bounds__(256) cvt4C(const float* s0, const float* s1,
                                             const float* s2, const float* s3,
                                             __half* d0, __half* d1,
                                             __half* d2, __half* d3) {
    const int seg = blockIdx.x >> 10;
    const int i = ((blockIdx.x & 1023) << 8) + threadIdx.x;
    const float* src = (seg == 0) ? s0 : (seg == 1) ? s1 : (seg == 2) ? s2 : s3;
    __half* dst      = (seg == 0) ? d0 : (seg == 1) ? d1 : (seg == 2) ? d2 : d3;
    ((uint2*)dst)[i] = f4_to_h4(((const float4*)src)[i]);
}

__global__ void __launch_bounds__(256) cvt2F(const float* s0, const float* s1,
                                             __half* d0, __half* d1) {
    const int seg = blockIdx.x >> 12;
    const int i = ((blockIdx.x & 4095) << 8) + threadIdx.x;
    const float* src = (seg == 0) ? s0 : s1;
    __half* dst      = (seg == 0) ? d0 : d1;
    ((uint2*)dst)[i] = f4_to_h4(((const float4*)src)[i]);
}

// wos pair: 2 strided C*C segments into g_wos (row stride 2048 halfs)
__global__ void __launch_bounds__(256) cvt_wos(const float* s0, const float* s1,
                                               __half* dst) {
    const int seg = blockIdx.x >> 10;
    const int i4 = ((blockIdx.x & 1023) << 8) + threadIdx.x;
    const float* src = (seg == 0) ? s0 : s1;
    const int off = (seg == 0) ? 0 : 256;
    const int row = i4 >> 8;
    const int col = i4 & 255;
    ((uint2*)dst)[(size_t)row * 512 + off + col] = f4_to_h4(((const float4*)src)[i4]);
}

// ---------------------------------------------------------------------------
// Fused LayerNorm + time-shift-mix.
// NOUT=3 additionally writes the raw x row (half) into xout (ao right half).
// ---------------------------------------------------------------------------
#define ROWS_PB 32

template <int NOUT>
__global__ void __launch_bounds__(256) ln_mix_kernel(
        const float* __restrict__ x,
        const float* __restrict__ w, const float* __restrict__ b,
        const float* __restrict__ m0, const float* __restrict__ m1,
        const float* __restrict__ m2,
        __half* __restrict__ o0, __half* __restrict__ o1,
        __half* __restrict__ o2, __half* __restrict__ xout) {
    __shared__ float sm_s[8], sm_ss[8];
    const int tid = threadIdx.x;
    const int wid = tid >> 5, lid = tid & 31;
    const size_t row0 = (size_t)blockIdx.x * ROWS_PB;
    const bool at_t0 = ((row0 & (T_ - 1)) == 0);

    const float4 wv = ((const float4*)w)[tid];
    const float4 bv = ((const float4*)b)[tid];
    const float4 mk0 = ((const float4*)m0)[tid];
    const float4 mk1 = ((const float4*)m1)[tid];
    const float4 mk2 = (NOUT == 3) ? ((const float4*)m2)[tid]
                                   : make_float4(0.f, 0.f, 0.f, 0.f);

    float4 raw;
    auto ln_row = [&](size_t row) -> float4 {
        float4 xv4 = ((const float4*)(x + row * C_))[tid];
        raw = xv4;
        float s  = xv4.x + xv4.y + xv4.z + xv4.w;
        float ss = xv4.x * xv4.x + xv4.y * xv4.y + xv4.z * xv4.z + xv4.w * xv4.w;
        #pragma unroll
        for (int o = 16; o > 0; o >>= 1) {
            s  += __shfl_down_sync(0xffffffffu, s,  o);
            ss += __shfl_down_sync(0xffffffffu, ss, o);
        }
        __syncthreads();
        if (lid == 0) { sm_s[wid] = s; sm_ss[wid] = ss; }
        __syncthreads();
        float ts = 0.f, tss = 0.f;
        #pragma unroll
        for (int q = 0; q < 8; ++q) { ts += sm_s[q]; tss += sm_ss[q]; }
        const float mean = ts * (1.0f / C_);
        const float var  = tss * (1.0f / C_) - mean * mean;
        const float rstd = rsqrtf(var + 1e-5f);
        float4 r;
        r.x = (xv4.x - mean) * rstd * wv.x + bv.x;
        r.y = (xv4.y - mean) * rstd * wv.y + bv.y;
        r.z = (xv4.z - mean) * rstd * wv.z + bv.z;
        r.w = (xv4.w - mean) * rstd * wv.w + bv.w;
        return r;
    };

    float4 prev = make_float4(0.f, 0.f, 0.f, 0.f);
    if (!at_t0) prev = ln_row(row0 - 1);

    for (int i = 0; i < ROWS_PB; ++i) {
        const size_t row = row0 + i;
        float4 cur = ln_row(row);
        const size_t o4 = row * (C_ / 4) + tid;

        {
            float a0 = cur.x * mk0.x + prev.x * (1.f - mk0.x);
            float a1 = cur.y * mk0.y + prev.y * (1.f - mk0.y);
            float a2 = cur.z * mk0.z + prev.z * (1.f - mk0.z);
            float a3 = cur.w * mk0.w + prev.w * (1.f - mk0.w);
            ((uint2*)o0)[o4] = f4_to_h4(make_float4(a0, a1, a2, a3));
        }
        {
            float a0 = cur.x * mk1.x + prev.x * (1.f - mk1.x);
            float a1 = cur.y * mk1.y + prev.y * (1.f - mk1.y);
            float a2 = cur.z * mk1.z + prev.z * (1.f - mk1.z);
            float a3 = cur.w * mk1.w + prev.w * (1.f - mk1.w);
            ((uint2*)o1)[o4] = f4_to_h4(make_float4(a0, a1, a2, a3));
        }
        if (NOUT == 3) {
            float a0 = cur.x * mk2.x + prev.x * (1.f - mk2.x);
            float a1 = cur.y * mk2.y + prev.y * (1.f - mk2.y);
            float a2 = cur.z * mk2.z + prev.z * (1.f - mk2.z);
            float a3 = cur.w * mk2.w + prev.w * (1.f - mk2.w);
            ((uint2*)o2)[o4] = f4_to_h4(make_float4(a0, a1, a2, a3));
            ((uint2*)xout)[row * 512 + 256 + tid] = f4_to_h4(raw);
        }
        prev = cur;
    }
}

// ---------------------------------------------------------------------------
// WKV chunk-parallel scan, UNNORMALIZED form
// ---------------------------------------------------------------------------
__global__ void __launch_bounds__(256) wkv_part(const float* __restrict__ decay,
                                                const float* __restrict__ ek,
                                                const float* __restrict__ v) {
    int gid = blockIdx.x * blockDim.x + threadIdx.x;
    int j    = gid >> 13;
    int chan = gid & (NCHAN - 1);
    int b = chan >> 10;
    int c = chan & (C_ - 1);
    const float ew = __expf(-__expf(decay[c]));
    size_t off = ((size_t)b * T_ + (size_t)j * CHL) * C_ + c;

    float a = 0.f, bb = 0.f;
    #pragma unroll 4
    for (int t = 0; t < CHL; ++t, off += C_) {
        const float e = ek[off];
        const float vt = v[off];
        a  = fmaf(ew, a, e * vt);
        bb = fmaf(ew, bb, e);
    }
    g_sa[j * NCHAN + chan] = a;
    g_sb[j * NCHAN + chan] = bb;
}

__global__ void __launch_bounds__(256) wkv_scan(const float* __restrict__ decay) {
    int chan = blockIdx.x * blockDim.x + threadIdx.x;
    if (chan >= NCHAN) return;
    int c = chan & (C_ - 1);
    const float w = -__expf(decay[c]);
    const float dw = __expf((float)CHL * w);

    float a = 0.f, bb = 0.f;
    #pragma unroll
    for (int j = 0; j < NCH; ++j) {
        g_pa[j * NCHAN + chan] = a;
        g_pb[j * NCHAN + chan] = bb;
        a  = fmaf(a,  dw, g_sa[j * NCHAN + chan]);
        bb = fmaf(bb, dw, g_sb[j * NCHAN + chan]);
    }
}

__global__ void __launch_bounds__(256) wkv_out(const float* __restrict__ decay,
                                               const float* __restrict__ first,
                                               const float* __restrict__ ek,
                                               const float* __restrict__ v,
                                               const float* __restrict__ r,
                                               __half* __restrict__ out) {
    int gid = blockIdx.x * blockDim.x + threadIdx.x;
    int j    = gid >> 13;
    int chan = gid & (NCHAN - 1);
    int b = chan >> 10;
    int c = chan & (C_ - 1);
    const float ew = __expf(-__expf(decay[c]));
    const float eu = __expf(first[c]);
    size_t off  = ((size_t)b * T_ + (size_t)j * CHL) * C_ + c;
    size_t offo = ((size_t)b * T_ + (size_t)j * CHL) * 2048 + c;

    float a  = g_pa[j * NCHAN + chan];
    float bb = g_pb[j * NCHAN + chan];

    #pragma unroll 4
    for (int t = 0; t < CHL; ++t, off += C_, offo += 2048) {
        const float e  = ek[off];
        const float vt = v[off];
        const float x  = eu * e;
        const float y  = __fdividef(fmaf(x, vt, a), bb + x);
        out[offo] = __float2half_rn(y * r[off]);
        a  = fmaf(ew, a, e * vt);
        bb = fmaf(ew, bb, e);
    }
}

// ---------------------------------------------------------------------------
// fp16 tensor-core GEMM core: 128x128 CTA tile, BK=32 halfs, 256 threads
// (8 warps @ 64x32), 4 stages, __syncthreads every TWO k-iterations
// (window protocol: wait all loads -> sync -> prefetch 2 stages -> 64 HMMA),
// 2 CTAs/SM, ldmatrix fragment loads.
// ---------------------------------------------------------------------------
#define BM 128
#define BN 128
#define BK 32
#define BKPH 40
#define STG 4
#define STAGE_HALFS (128 * BKPH)
#define GEMM_SMEM (STG * STAGE_HALFS * 2 * 2)   // 81920 bytes

struct GemmCtx {
    uint32_t aBase, bBase;
    int lrow, lk;
    const __half* Ag;
    const __half* Wg;
    __half* AsBase;
    __half* BsBase;
};

// one k-subtile (16 halfs) of one stage: 6 ldmatrix + 16 mma
__device__ __forceinline__ void gemm_kstep(GemmCtx& cx, float acc[4][4][4],
                                           uint32_t soff, uint32_t koff) {
    uint32_t af[4][4], b0[4], b1[4];
    ldsm_x4(b0, cx.bBase + soff + koff);
    ldsm_x4(b1, cx.bBase + soff + koff + 16 * BKPH * 2);
    #pragma unroll
    for (int mt = 0; mt < 4; ++mt)
        ldsm_x4(af[mt], cx.aBase + soff + koff + (uint32_t)mt * (16 * BKPH * 2));
    #pragma unroll
    for (int mt = 0; mt < 4; ++mt) {
        mma_f16(acc[mt][0], af[mt], b0);
        mma_f16(acc[mt][1], af[mt], b0 + 2);
        mma_f16(acc[mt][2], af[mt], b1);
        mma_f16(acc[mt][3], af[mt], b1 + 2);
    }
}

__device__ __forceinline__ void gemm_main(GemmCtx& cx, float acc[4][4][4], int K) {
    auto load_stage = [&](int s, int k0) {
        __half* a = cx.AsBase + s * STAGE_HALFS + cx.lrow * BKPH + cx.lk;
        __half* b = cx.BsBase + s * STAGE_HALFS + cx.lrow * BKPH + cx.lk;
        cp_async16(a,     cx.Ag + k0);
        cp_async16(a + 8, cx.Ag + k0 + 8);
        cp_async16(b,     cx.Wg + k0);
        cp_async16(b + 8, cx.Wg + k0 + 8);
    };

    // prologue: stages for the first window
    load_stage(0, 0);  CP_COMMIT();
    load_stage(1, BK); CP_COMMIT();

    const int nk = K / BK;     // always even here (32/64/128)
    for (int it = 0; it < nk; it += 2) {
        CP_WAIT0();            // both stages of this window are resident
        __syncthreads();       // everyone done reading the window's slots

        const uint32_t s0 = (uint32_t)(it & 3) * (STAGE_HALFS * 2);
        const uint32_t s1 = (uint32_t)((it + 1) & 3) * (STAGE_HALFS * 2);

        // iter it, ks=0 fragments first to get mma going, then prefetch
        {
            uint32_t af[4][4], b0[4], b1[4];
            ldsm_x4(b0, cx.bBase + s0);
            ldsm_x4(b1, cx.bBase + s0 + 16 * BKPH * 2);
            #pragma unroll
            for (int mt = 0; mt < 4; ++mt)
                ldsm_x4(af[mt], cx.aBase + s0 + (uint32_t)mt * (16 * BKPH * 2));

            // prefetch next window's two stages (slots last read before the
            // sync above -> race-free)
            if (it + 2 < nk) { load_stage((it + 2) & 3, (it + 2) * BK); CP_COMMIT(); }
            if (it + 3 < nk) { load_stage((it + 3) & 3, (it + 3) * BK); CP_COMMIT(); }

            #pragma unroll
            for (int mt = 0; mt < 4; ++mt) {
                mma_f16(acc[mt][0], af[mt], b0);
                mma_f16(acc[mt][1], af[mt], b0 + 2);
                mma_f16(acc[mt][2], af[mt], b1);
                mma_f16(acc[mt][3], af[mt], b1 + 2);
            }
        }
        gemm_kstep(cx, acc, s0, 32);   // iter it, ks=1
        gemm_kstep(cx, acc, s1, 0);    // iter it+1, ks=0
        gemm_kstep(cx, acc, s1, 32);   // iter it+1, ks=1
    }
}

__device__ __forceinline__ void gemm_setup(GemmCtx& cx, const __half* A,
                                           const __half* W, int K,
                                           __half* smh) {
    const int tid  = threadIdx.x;
    const int wid  = tid >> 5;
    const int lane = tid & 31;
    cx.AsBase = smh;
    cx.BsBase = smh + STG * STAGE_HALFS;
    cx.lrow = tid >> 1;
    cx.lk   = (tid & 1) * 16;
    cx.Ag = A + ((size_t)blockIdx.y * BM + cx.lrow) * (size_t)K + cx.lk;
    cx.Wg = W + ((size_t)blockIdx.x * BN + cx.lrow) * (size_t)K + cx.lk;
    const int warp_m = wid >> 2;
    const int warp_n = wid & 3;
    const uint32_t smA = (uint32_t)__cvta_generic_to_shared(cx.AsBase);
    const uint32_t smB = (uint32_t)__cvta_generic_to_shared(cx.BsBase);
    cx.aBase = smA +
        (((uint32_t)(warp_m * 64 + (lane & 15)) * BKPH + (uint32_t)(lane >> 4) * 8) << 1);
    cx.bBase = smB +
        (((uint32_t)(warp_n * 32 + ((lane >> 4) << 3) + (lane & 7)) * BKPH +
          (uint32_t)((lane >> 3) & 1) * 8) << 1);
}

#define ZERO_ACC(acc)                                                          \
    _Pragma("unroll")                                                          \
    for (int i = 0; i < 4; ++i)                                                \
        _Pragma("unroll")                                                      \
        for (int j = 0; j < 4; ++j)                                            \
            _Pragma("unroll")                                                  \
            for (int r = 0; r < 4; ++r) acc[i][j][r] = 0.f;

#define EPI_LOOP(BODY)                                                         \
    const int tid  = threadIdx.x;                                              \
    const int wid  = tid >> 5;                                                 \
    const int lane = tid & 31;                                                 \
    const int g    = lane >> 2;                                                \
    const int tig  = lane & 3;                                                 \
    const int warp_m = wid >> 2;                                               \
    const int warp_n = wid & 3;                                                \
    _Pragma("unroll")                                                          \
    for (int mt = 0; mt < 4; ++mt) {                                           \
        const int r0 = (int)(blockIdx.y * BM) + warp_m * 64 + mt * 16 + g;     \
        _Pragma("unroll")                                                      \
        for (int nt = 0; nt < 4; ++nt) {                                       \
            const int c0 = (int)(blockIdx.x * BN) + warp_n * 32 + nt * 8 + 2 * tig; \
            _Pragma("unroll")                                                  \
            for (int hi = 0; hi < 2; ++hi) {                                   \
                const int row = r0 + hi * 8;                                   \
                const size_t off = (size_t)row * N + c0;                       \
                float v0 = acc[mt][nt][hi * 2 + 0];                            \
                float v1 = acc[mt][nt][hi * 2 + 1];                            \
                BODY                                                           \
            }                                                                  \
        }                                                                      \
    }

// Single GEMM, MODE: 0 store f32, 2 relu^2->half
template <int MODE>
__global__ void __launch_bounds__(256, 2) gemm_tc(const __half* __restrict__ A,
                                                  const __half* __restrict__ W,
                                                  void* __restrict__ Cc,
                                                  int N, int K) {
    extern __shared__ __half smh[];
    GemmCtx cx;
    gemm_setup(cx, A, W, K, smh);
    float acc[4][4][4];
    ZERO_ACC(acc)
    gemm_main(cx, acc, K);

    EPI_LOOP({
        if (MODE == 2) {
            v0 = fmaxf(v0, 0.f); v0 = v0 * v0;
            v1 = fmaxf(v1, 0.f); v1 = v1 * v1;
            __half2 hv = __floats2half2_rn(v0, v1);
            *(__half2*)((__half*)Cc + off) = hv;
        } else {
            float2 o; o.x = v0; o.y = v1;
            *(float2*)((float*)Cc + off) = o;
        }
    })
}

// Batched TimeMix triple GEMM: z=0 exp(k), z=1 v, z=2 sigmoid(r)
__global__ void __launch_bounds__(256, 2) gemm_tc3(
        const __half* __restrict__ A0, const __half* __restrict__ A1,
        const __half* __restrict__ A2,
        const __half* __restrict__ W0, const __half* __restrict__ W1,
        const __half* __restrict__ W2,
        float* __restrict__ C0, float* __restrict__ C1,
        float* __restrict__ C2, int N, int K) {
    extern __shared__ __half smh[];
    const int z = blockIdx.z;
    const __half* A = (z == 0) ? A0 : (z == 1) ? A1 : A2;
    const __half* W = (z == 0) ? W0 : (z == 1) ? W1 : W2;
    float* Cc       = (z == 0) ? C0 : (z == 1) ? C1 : C2;

    GemmCtx cx;
    gemm_setup(cx, A, W, K, smh);
    float acc[4][4][4];
    ZERO_ACC(acc)
    gemm_main(cx, acc, K);

    EPI_LOOP({
        if (z == 0) {
            v0 = __expf(v0); v1 = __expf(v1);
        } else if (z == 2) {
            v0 = 1.f / (1.f + __expf(-v0));
            v1 = 1.f / (1.f + __expf(-v1));
        }
        float2 o; o.x = v0; o.y = v1;
        *(float2*)(Cc + off) = o;
    })
}

// Fused FFN tail: acc_r = gr@fWr^T (K=1024) -> sigmoid -> packed half;
// acc_kv = kk@fWv^T (K=4096); out = x2 + sigmoid_r * kv.
__global__ void __launch_bounds__(256, 2) gemm_fuse(
        const __half* __restrict__ Ar, const __half* __restrict__ Wr_,
        const __half* __restrict__ Akv, const __half* __restrict__ Wkv,
        const float* __restrict__ x2, float* __restrict__ out) {
    extern __shared__ __half smh[];
    float acc[4][4][4];

    {
        GemmCtx cx;
        gemm_setup(cx, Ar, Wr_, C_, smh);
        ZERO_ACC(acc)
        gemm_main(cx, acc, C_);
    }

    uint32_t rpack[4][4][2];
    #pragma unroll
    for (int mt = 0; mt < 4; ++mt)
        #pragma unroll
        for (int nt = 0; nt < 4; ++nt) {
            float s0 = 1.f / (1.f + __expf(-acc[mt][nt][0]));
            float s1 = 1.f / (1.f + __expf(-acc[mt][nt][1]));
            float s2 = 1.f / (1.f + __expf(-acc[mt][nt][2]));
            float s3 = 1.f / (1.f + __expf(-acc[mt][nt][3]));
            __half2 p0 = __floats2half2_rn(s0, s1);
            __half2 p1 = __floats2half2_rn(s2, s3);
            rpack[mt][nt][0] = *(uint32_t*)&p0;
            rpack[mt][nt][1] = *(uint32_t*)&p1;
        }

    __syncthreads();

    {
        GemmCtx cx;
        gemm_setup(cx, Akv, Wkv, F_, smh);
        ZERO_ACC(acc)
        gemm_main(cx, acc, F_);
    }

    const int N = C_;
    EPI_LOOP({
        float2 a1 = *(const float2*)(x2 + off);
        __half2 hp = *(__half2*)&rpack[mt][nt][hi];
        float2 rr = __half22float2(hp);
        v0 = a1.x + rr.x * v0;
        v1 = a1.y + rr.y * v1;
        float2 o; o.x = v0; o.y = v1;
        *(float2*)(out + off) = o;
    })
}

// ---------------------------------------------------------------------------
// Launch
// ---------------------------------------------------------------------------
template <typename T>
static T* sym(const void* s) {
    void* p = nullptr;
    cudaGetSymbolAddress(&p, s);
    return (T*)p;
}

extern "C" void kernel_launch(void* const* d_in, const int* in_sizes, int n_in,
                              void* d_out, int out_size) {
    const float* x        = (const float*)d_in[0];
    const float* ln1_w    = (const float*)d_in[1];
    const float* ln1_b    = (const float*)d_in[2];
    const float* ln2_w    = (const float*)d_in[3];
    const float* ln2_b    = (const float*)d_in[4];
    const float* t_decay  = (const float*)d_in[5];
    const float* t_first  = (const float*)d_in[6];
    const float* mix_k    = (const float*)d_in[7];
    const float* mix_v    = (const float*)d_in[8];
    const float* mix_r    = (const float*)d_in[9];
    const float* Wk       = (const float*)d_in[10];
    const float* Wv       = (const float*)d_in[11];
    const float* Wr       = (const float*)d_in[12];
    const float* Wo       = (const float*)d_in[13];
    const float* fmix_k   = (const float*)d_in[14];
    const float* fmix_r   = (const float*)d_in[15];
    const float* fWk      = (const float*)d_in[16];   // [F, C]
    const float* fWr      = (const float*)d_in[17];   // [C, C]
    const float* fWv      = (const float*)d_in[18];   // [C, F]
    const float* shortW   = (const float*)d_in[19];
    float* out = (float*)d_out;

    __half* xk   = sym<__half>(g_xk);
    __half* xv   = sym<__half>(g_xv);
    __half* xr   = sym<__half>(g_xr);
    float*  ekb  = sym<float>(g_ek);
    float*  vbuf = sym<float>(g_v);
    float*  rbuf = sym<float>(g_r);
    __half* ao   = sym<__half>(g_ao);
    float*  x2   = sym<float>(g_x2);
    __half* gk   = sym<__half>(g_gk);
    __half* gr   = sym<__half>(g_gr);
    __half* kkb  = sym<__half>(g_kk);
    __half* wkt  = sym<__half>(g_wkt);
    __half* wvt  = sym<__half>(g_wvt);
    __half* wrt  = sym<__half>(g_wrt);
    __half* wos  = sym<__half>(g_wos);
    __half* fwrt = sym<__half>(g_fwrt);
    __half* fwkt = sym<__half>(g_fwkt);
    __half* fwvt = sym<__half>(g_fwvt);

    cudaFuncSetAttribute(gemm_tc<0>, cudaFuncAttributeMaxDynamicSharedMemorySize, GEMM_SMEM);
    cudaFuncSetAttribute(gemm_tc<2>, cudaFuncAttributeMaxDynamicSharedMemorySize, GEMM_SMEM);
    cudaFuncSetAttribute(gemm_tc3, cudaFuncAttributeMaxDynamicSharedMemorySize, GEMM_SMEM);
    cudaFuncSetAttribute(gemm_fuse, cudaFuncAttributeMaxDynamicSharedMemorySize, GEMM_SMEM);

    const dim3 blk(256);
    const dim3 grid_gC(C_ / BN, M_ / BM);        // (8, 128)
    const dim3 grid_gC3(C_ / BN, M_ / BM, 3);    // batched triple
    const dim3 grid_gF(F_ / BN, M_ / BM);        // (32, 128)
    const dim3 grid_lnmix(M_ / ROWS_PB);         // 512

    // 1: merged C-weight cvt (wk, wv, wr, fWr)
    cvt4C<<<4096, blk>>>(Wk, Wv, Wr, fWr, wkt, wvt, wrt, fwrt);
    // 2: LN1 + mix (+ writes x->half into ao right half)
    ln_mix_kernel<3><<<grid_lnmix, blk>>>(x, ln1_w, ln1_b,
                                          mix_k, mix_v, mix_r, xk, xv, xr, ao);
    // 3: wos pair (Wo | shortW)
    cvt_wos<<<2048, blk>>>(Wo, shortW, wos);
    // 4: TimeMix triple GEMM  <-- ncu capture target
    gemm_tc3<<<grid_gC3, blk, GEMM_SMEM>>>(xk, xv, xr, wkt, wvt, wrt,
                                           ekb, vbuf, rbuf, C_, C_);
    // 5: merged F-weight cvt (fWk, fWv) — needed later only
    cvt2F<<<8192, blk>>>(fWk, fWv, fwkt, fwvt);
    wkv_part<<<(NCHAN * NCH) / 256, blk>>>(t_decay, ekb, vbuf);
    wkv_scan<<<NCHAN / 256, blk>>>(t_decay);
    wkv_out<<<(NCHAN * NCH) / 256, blk>>>(t_decay, t_first, ekb, vbuf, rbuf, ao);
    // x2 = [rwkv | x] @ [Wo | shortW]^T   (K = 2048)
    gemm_tc<0><<<grid_gC, blk, GEMM_SMEM>>>(ao, wos, x2, C_, 2048);

    // --- ChannelMix path ---
    ln_mix_kernel<2><<<grid_lnmix, blk>>>(x2, ln2_w, ln2_b,
                                          fmix_k, fmix_r, nullptr, gk, gr,
                                          nullptr, nullptr);
    gemm_tc<2><<<grid_gF, blk, GEMM_SMEM>>>(gk, fwkt, kkb, F_, C_);
    gemm_fuse<<<grid_gC, blk, GEMM_SMEM>>>(gr, fwrt, kkb, fwvt, x2, out);
}

// round 17
// speedup vs baseline: 1.0222x; 1.0049x over previous
#include <cuda_runtime.h>
#include <cuda_fp16.h>
#include <math.h>
#include <stdint.h>

// Problem dims (fixed by the reference)
#define B_ 8
#define T_ 2048
#define C_ 1024
#define F_ 4096
#define M_ (B_ * T_)   // 16384 rows

constexpr size_t S_  = (size_t)M_ * C_;   // 16,777,216
constexpr size_t SF_ = (size_t)M_ * F_;   // 67,108,864
constexpr size_t CC_ = (size_t)C_ * C_;
constexpr size_t FC_ = (size_t)F_ * C_;

#define NCH 32            // WKV chunks
#define CHL (T_ / NCH)    // 64 steps per chunk
#define NCHAN (B_ * C_)   // 8192 channels

// ---------------------------------------------------------------------------
// Scratch (static device globals — allocation-free per harness rules)
// ---------------------------------------------------------------------------
__device__ __half g_xk[S_];
__device__ __half g_xv[S_];
__device__ __half g_xr[S_];
__device__ float  g_ek[S_];     // exp(k)  (from Wk GEMM epilogue)
__device__ float  g_v[S_];
__device__ float  g_r[S_];      // sigmoid(r)
__device__ __half g_ao[(size_t)M_ * 2048];  // [rwkv | x_half] along K
__device__ float  g_x2[S_];
__device__ __half g_gk[S_];
__device__ __half g_gr[S_];
__device__ __half g_kk[SF_];
// half weights
__device__ __half g_wkt[CC_];
__device__ __half g_wvt[CC_];
__device__ __half g_wrt[CC_];
__device__ __half g_wos[2 * CC_];  // [Wo | shortW] along K
__device__ __half g_fwrt[CC_];
__device__ __half g_fwkt[FC_];
__device__ __half g_fwvt[FC_];
// WKV chunk-scan state (a, b per chunk)
__device__ float g_sa[NCHAN * NCH], g_sb[NCHAN * NCH];
__device__ float g_pa[NCHAN * NCH], g_pb[NCHAN * NCH];

// ---------------------------------------------------------------------------
// helpers
// ---------------------------------------------------------------------------
__device__ __forceinline__ void cp_async16(void* smem, const void* gmem) {
    uint32_t s = (uint32_t)__cvta_generic_to_shared(smem);
    asm volatile("cp.async.cg.shared.global [%0], [%1], 16;" :: "r"(s), "l"(gmem));
}
#define CP_COMMIT() asm volatile("cp.async.commit_group;")
#define CP_WAIT0()  asm volatile("cp.async.wait_group 0;")

__device__ __forceinline__ void mma_f16(float* d, const uint32_t* a, const uint32_t* b) {
    asm volatile(
        "mma.sync.aligned.m16n8k16.row.col.f32.f16.f16.f32 "
        "{%0,%1,%2,%3}, {%4,%5,%6,%7}, {%8,%9}, {%0,%1,%2,%3};"
        : "+f"(d[0]), "+f"(d[1]), "+f"(d[2]), "+f"(d[3])
        : "r"(a[0]), "r"(a[1]), "r"(a[2]), "r"(a[3]),
          "r"(b[0]), "r"(b[1]));
}

__device__ __forceinline__ void ldsm_x4(uint32_t* r, uint32_t addr) {
    asm volatile("ldmatrix.sync.aligned.m8n8.x4.shared.b16 {%0,%1,%2,%3}, [%4];"
        : "=r"(r[0]), "=r"(r[1]), "=r"(r[2]), "=r"(r[3]) : "r"(addr));
}

__device__ __forceinline__ uint2 f4_to_h4(float4 v) {
    __half2 h0 = __floats2half2_rn(v.x, v.y);
    __half2 h1 = __floats2half2_rn(v.z, v.w);
    uint2 o;
    o.x = *(uint32_t*)&h0;
    o.y = *(uint32_t*)&h1;
    return o;
}

// ---------------------------------------------------------------------------
// Merged cvt kernels
// ---------------------------------------------------------------------------
__global__ void __launch_bounds__(256) cvt4C(const float* s0, const float* s1,
                                             const float* s2, const float* s3,
                                             __half* d0, __half* d1,
                                             __half* d2, __half* d3) {
    const int seg = blockIdx.x >> 10;
    const int i = ((blockIdx.x & 1023) << 8) + threadIdx.x;
    const float* src = (seg == 0) ? s0 : (seg == 1) ? s1 : (seg == 2) ? s2 : s3;
    __half* dst      = (seg == 0) ? d0 : (seg == 1) ? d1 : (seg == 2) ? d2 : d3;
    ((uint2*)dst)[i] = f4_to_h4(((const float4*)src)[i]);
}

__global__ void __launch_bounds__(256) cvt2F(const float* s0, const float* s1,
                                             __half* d0, __half* d1) {
    const int seg = blockIdx.x >> 12;
    const int i = ((blockIdx.x & 4095) << 8) + threadIdx.x;
    const float* src = (seg == 0) ? s0 : s1;
    __half* dst      = (seg == 0) ? d0 : d1;
    ((uint2*)dst)[i] = f4_to_h4(((const float4*)src)[i]);
}

// wos pair: 2 strided C*C segments into g_wos (row stride 2048 halfs)
__global__ void __launch_bounds__(256) cvt_wos(const float* s0, const float* s1,
                                               __half* dst) {
    const int seg = blockIdx.x >> 10;
    const int i4 = ((blockIdx.x & 1023) << 8) + threadIdx.x;
    const float* src = (seg == 0) ? s0 : s1;
    const int off = (seg == 0) ? 0 : 256;
    const int row = i4 >> 8;
    const int col = i4 & 255;
    ((uint2*)dst)[(size_t)row * 512 + off + col] = f4_to_h4(((const float4*)src)[i4]);
}

// ---------------------------------------------------------------------------
// Fused LayerNorm + time-shift-mix.
// NOUT=3 additionally writes the raw x row (half) into xout (ao right half).
// ---------------------------------------------------------------------------
#define ROWS_PB 16

template <int NOUT>
__global__ void __launch_bounds__(256) ln_mix_kernel(
        const float* __restrict__ x,
        const float* __restrict__ w, const float* __restrict__ b,
        const float* __restrict__ m0, const float* __restrict__ m1,
        const float* __restrict__ m2,
        __half* __restrict__ o0, __half* __restrict__ o1,
        __half* __restrict__ o2, __half* __restrict__ xout) {
    __shared__ float sm_s[8], sm_ss[8];
    const int tid = threadIdx.x;
    const int wid = tid >> 5, lid = tid & 31;
    const size_t row0 = (size_t)blockIdx.x * ROWS_PB;
    const bool at_t0 = ((row0 & (T_ - 1)) == 0);

    const float4 wv = ((const float4*)w)[tid];
    const float4 bv = ((const float4*)b)[tid];
    const float4 mk0 = ((const float4*)m0)[tid];
    const float4 mk1 = ((const float4*)m1)[tid];
    const float4 mk2 = (NOUT == 3) ? ((const float4*)m2)[tid]
                                   : make_float4(0.f, 0.f, 0.f, 0.f);

    float4 raw;
    auto ln_row = [&](size_t row) -> float4 {
        float4 xv4 = ((const float4*)(x + row * C_))[tid];
        raw = xv4;
        float s  = xv4.x + xv4.y + xv4.z + xv4.w;
        float ss = xv4.x * xv4.x + xv4.y * xv4.y + xv4.z * xv4.z + xv4.w * xv4.w;
        #pragma unroll
        for (int o = 16; o > 0; o >>= 1) {
            s  += __shfl_down_sync(0xffffffffu, s,  o);
            ss += __shfl_down_sync(0xffffffffu, ss, o);
        }
        __syncthreads();
        if (lid == 0) { sm_s[wid] = s; sm_ss[wid] = ss; }
        __syncthreads();
        float ts = 0.f, tss = 0.f;
        #pragma unroll
        for (int q = 0; q < 8; ++q) { ts += sm_s[q]; tss += sm_ss[q]; }
        const float mean = ts * (1.0f / C_);
        const float var  = tss * (1.0f / C_) - mean * mean;
        const float rstd = rsqrtf(var + 1e-5f);
        float4 r;
        r.x = (xv4.x - mean) * rstd * wv.x + bv.x;
        r.y = (xv4.y - mean) * rstd * wv.y + bv.y;
        r.z = (xv4.z - mean) * rstd * wv.z + bv.z;
        r.w = (xv4.w - mean) * rstd * wv.w + bv.w;
        return r;
    };

    float4 prev = make_float4(0.f, 0.f, 0.f, 0.f);
    if (!at_t0) prev = ln_row(row0 - 1);

    for (int i = 0; i < ROWS_PB; ++i) {
        const size_t row = row0 + i;
        float4 cur = ln_row(row);
        const size_t o4 = row * (C_ / 4) + tid;

        {
            float a0 = cur.x * mk0.x + prev.x * (1.f - mk0.x);
            float a1 = cur.y * mk0.y + prev.y * (1.f - mk0.y);
            float a2 = cur.z * mk0.z + prev.z * (1.f - mk0.z);
            float a3 = cur.w * mk0.w + prev.w * (1.f - mk0.w);
            ((uint2*)o0)[o4] = f4_to_h4(make_float4(a0, a1, a2, a3));
        }
        {
            float a0 = cur.x * mk1.x + prev.x * (1.f - mk1.x);
            float a1 = cur.y * mk1.y + prev.y * (1.f - mk1.y);
            float a2 = cur.z * mk1.z + prev.z * (1.f - mk1.z);
            float a3 = cur.w * mk1.w + prev.w * (1.f - mk1.w);
            ((uint2*)o1)[o4] = f4_to_h4(make_float4(a0, a1, a2, a3));
        }
        if (NOUT == 3) {
            float a0 = cur.x * mk2.x + prev.x * (1.f - mk2.x);
            float a1 = cur.y * mk2.y + prev.y * (1.f - mk2.y);
            float a2 = cur.z * mk2.z + prev.z * (1.f - mk2.z);
            float a3 = cur.w * mk2.w + prev.w * (1.f - mk2.w);
            ((uint2*)o2)[o4] = f4_to_h4(make_float4(a0, a1, a2, a3));
            ((uint2*)xout)[row * 512 + 256 + tid] = f4_to_h4(raw);
        }
        prev = cur;
    }
}

// ---------------------------------------------------------------------------
// WKV chunk-parallel scan, UNNORMALIZED form (NCH=32 chunks)
// ---------------------------------------------------------------------------
__global__ void __launch_bounds__(256) wkv_part(const float* __restrict__ decay,
                                                const float* __restrict__ ek,
                                                const float* __restrict__ v) {
    int gid = blockIdx.x * blockDim.x + threadIdx.x;   // NCHAN*NCH = 262144
    int j    = gid >> 13;          // chunk 0..31
    int chan = gid & (NCHAN - 1);
    int b = chan >> 10;
    int c = chan & (C_ - 1);
    const float ew = __expf(-__expf(decay[c]));
    size_t off = ((size_t)b * T_ + (size_t)j * CHL) * C_ + c;

    float a = 0.f, bb = 0.f;
    #pragma unroll 4
    for (int t = 0; t < CHL; ++t, off += C_) {
        const float e = ek[off];
        const float vt = v[off];
        a  = fmaf(ew, a, e * vt);
        bb = fmaf(ew, bb, e);
    }
    g_sa[j * NCHAN + chan] = a;
    g_sb[j * NCHAN + chan] = bb;
}

__global__ void __launch_bounds__(256) wkv_scan(const float* __restrict__ decay) {
    int chan = blockIdx.x * blockDim.x + threadIdx.x;
    if (chan >= NCHAN) return;
    int c = chan & (C_ - 1);
    const float w = -__expf(decay[c]);
    const float dw = __expf((float)CHL * w);

    float a = 0.f, bb = 0.f;
    #pragma unroll
    for (int j = 0; j < NCH; ++j) {
        g_pa[j * NCHAN + chan] = a;
        g_pb[j * NCHAN + chan] = bb;
        a  = fmaf(a,  dw, g_sa[j * NCHAN + chan]);
        bb = fmaf(bb, dw, g_sb[j * NCHAN + chan]);
    }
}

__global__ void __launch_bounds__(256) wkv_out(const float* __restrict__ decay,
                                               const float* __restrict__ first,
                                               const float* __restrict__ ek,
                                               const float* __restrict__ v,
                                               const float* __restrict__ r,
                                               __half* __restrict__ out) {
    int gid = blockIdx.x * blockDim.x + threadIdx.x;
    int j    = gid >> 13;
    int chan = gid & (NCHAN - 1);
    int b = chan >> 10;
    int c = chan & (C_ - 1);
    const float ew = __expf(-__expf(decay[c]));
    const float eu = __expf(first[c]);
    size_t off  = ((size_t)b * T_ + (size_t)j * CHL) * C_ + c;
    size_t offo = ((size_t)b * T_ + (size_t)j * CHL) * 2048 + c;

    float a  = g_pa[j * NCHAN + chan];
    float bb = g_pb[j * NCHAN + chan];

    #pragma unroll 4
    for (int t = 0; t < CHL; ++t, off += C_, offo += 2048) {
        const float e  = ek[off];
        const float vt = v[off];
        const float x  = eu * e;
        const float y  = __fdividef(fmaf(x, vt, a), bb + x);
        out[offo] = __float2half_rn(y * r[off]);
        a  = fmaf(ew, a, e * vt);
        bb = fmaf(ew, bb, e);
    }
}

// ---------------------------------------------------------------------------
// fp16 tensor-core GEMM core: 128x128 CTA tile, BK=32 halfs, 256 threads
// (8 warps @ 64x32), 4 stages, __syncthreads every TWO k-iterations,
// 2 CTAs/SM, ldmatrix fragment loads.  (R16 winner — unchanged)
// ---------------------------------------------------------------------------
#define BM 128
#define BN 128
#define BK 32
#define BKPH 40
#define STG 4
#define STAGE_HALFS (128 * BKPH)
#define GEMM_SMEM (STG * STAGE_HALFS * 2 * 2)   // 81920 bytes

struct GemmCtx {
    uint32_t aBase, bBase;
    int lrow, lk;
    const __half* Ag;
    const __half* Wg;
    __half* AsBase;
    __half* BsBase;
};

// one k-subtile (16 halfs) of one stage: 6 ldmatrix + 16 mma
__device__ __forceinline__ void gemm_kstep(GemmCtx& cx, float acc[4][4][4],
                                           uint32_t soff, uint32_t koff) {
    uint32_t af[4][4], b0[4], b1[4];
    ldsm_x4(b0, cx.bBase + soff + koff);
    ldsm_x4(b1, cx.bBase + soff + koff + 16 * BKPH * 2);
    #pragma unroll
    for (int mt = 0; mt < 4; ++mt)
        ldsm_x4(af[mt], cx.aBase + soff + koff + (uint32_t)mt * (16 * BKPH * 2));
    #pragma unroll
    for (int mt = 0; mt < 4; ++mt) {
        mma_f16(acc[mt][0], af[mt], b0);
        mma_f16(acc[mt][1], af[mt], b0 + 2);
        mma_f16(acc[mt][2], af[mt], b1);
        mma_f16(acc[mt][3], af[mt], b1 + 2);
    }
}

__device__ __forceinline__ void gemm_main(GemmCtx& cx, float acc[4][4][4], int K) {
    auto load_stage = [&](int s, int k0) {
        __half* a = cx.AsBase + s * STAGE_HALFS + cx.lrow * BKPH + cx.lk;
        __half* b = cx.BsBase + s * STAGE_HALFS + cx.lrow * BKPH + cx.lk;
        cp_async16(a,     cx.Ag + k0);
        cp_async16(a + 8, cx.Ag + k0 + 8);
        cp_async16(b,     cx.Wg + k0);
        cp_async16(b + 8, cx.Wg + k0 + 8);
    };

    load_stage(0, 0);  CP_COMMIT();
    load_stage(1, BK); CP_COMMIT();

    const int nk = K / BK;     // always even (32/64/128)
    for (int it = 0; it < nk; it += 2) {
        CP_WAIT0();
        __syncthreads();

        const uint32_t s0 = (uint32_t)(it & 3) * (STAGE_HALFS * 2);
        const uint32_t s1 = (uint32_t)((it + 1) & 3) * (STAGE_HALFS * 2);

        {
            uint32_t af[4][4], b0[4], b1[4];
            ldsm_x4(b0, cx.bBase + s0);
            ldsm_x4(b1, cx.bBase + s0 + 16 * BKPH * 2);
            #pragma unroll
            for (int mt = 0; mt < 4; ++mt)
                ldsm_x4(af[mt], cx.aBase + s0 + (uint32_t)mt * (16 * BKPH * 2));

            if (it + 2 < nk) { load_stage((it + 2) & 3, (it + 2) * BK); CP_COMMIT(); }
            if (it + 3 < nk) { load_stage((it + 3) & 3, (it + 3) * BK); CP_COMMIT(); }

            #pragma unroll
            for (int mt = 0; mt < 4; ++mt) {
                mma_f16(acc[mt][0], af[mt], b0);
                mma_f16(acc[mt][1], af[mt], b0 + 2);
                mma_f16(acc[mt][2], af[mt], b1);
                mma_f16(acc[mt][3], af[mt], b1 + 2);
            }
        }
        gemm_kstep(cx, acc, s0, 32);
        gemm_kstep(cx, acc, s1, 0);
        gemm_kstep(cx, acc, s1, 32);
    }
}

__device__ __forceinline__ void gemm_setup(GemmCtx& cx, const __half* A,
                                           const __half* W, int K,
                                           __half* smh) {
    const int tid  = threadIdx.x;
    const int wid  = tid >> 5;
    const int lane = tid & 31;
    cx.AsBase = smh;
    cx.BsBase = smh + STG * STAGE_HALFS;
    cx.lrow = tid >> 1;
    cx.lk   = (tid & 1) * 16;
    cx.Ag = A + ((size_t)blockIdx.y * BM + cx.lrow) * (size_t)K + cx.lk;
    cx.Wg = W + ((size_t)blockIdx.x * BN + cx.lrow) * (size_t)K + cx.lk;
    const int warp_m = wid >> 2;
    const int warp_n = wid & 3;
    const uint32_t smA = (uint32_t)__cvta_generic_to_shared(cx.AsBase);
    const uint32_t smB = (uint32_t)__cvta_generic_to_shared(cx.BsBase);
    cx.aBase = smA +
        (((uint32_t)(warp_m * 64 + (lane & 15)) * BKPH + (uint32_t)(lane >> 4) * 8) << 1);
    cx.bBase = smB +
        (((uint32_t)(warp_n * 32 + ((lane >> 4) << 3) + (lane & 7)) * BKPH +
          (uint32_t)((lane >> 3) & 1) * 8) << 1);
}

#define ZERO_ACC(acc)                                                          \
    _Pragma("unroll")                                                          \
    for (int i = 0; i < 4; ++i)                                                \
        _Pragma("unroll")                                                      \
        for (int j = 0; j < 4; ++j)                                            \
            _Pragma("unroll")                                                  \
            for (int r = 0; r < 4; ++r) acc[i][j][r] = 0.f;

#define EPI_LOOP(BODY)                                                         \
    const int tid  = threadIdx.x;                                              \
    const int wid  = tid >> 5;                                                 \
    const int lane = tid & 31;                                                 \
    const int g    = lane >> 2;                                                \
    const int tig  = lane & 3;                                                 \
    const int warp_m = wid >> 2;                                               \
    const int warp_n = wid & 3;                                                \
    _Pragma("unroll")                                                          \
    for (int mt = 0; mt < 4; ++mt) {                                           \
        const int r0 = (int)(blockIdx.y * BM) + warp_m * 64 + mt * 16 + g;     \
        _Pragma("unroll")                                                      \
        for (int nt = 0; nt < 4; ++nt) {                                       \
            const int c0 = (int)(blockIdx.x * BN) + warp_n * 32 + nt * 8 + 2 * tig; \
            _Pragma("unroll")                                                  \
            for (int hi = 0; hi < 2; ++hi) {                                   \
                const int row = r0 + hi * 8;                                   \
                const size_t off = (size_t)row * N + c0;                       \
                float v0 = acc[mt][nt][hi * 2 + 0];                            \
                float v1 = acc[mt][nt][hi * 2 + 1];                            \
                BODY                                                           \
            }                                                                  \
        }                                                                      \
    }

// Single GEMM, MODE: 0 store f32, 2 relu^2->half
template <int MODE>
__global__ void __launch_bounds__(256, 2) gemm_tc(const __half* __restrict__ A,
                                                  const __half* __restrict__ W,
                                                  void* __restrict__ Cc,
                                                  int N, int K) {
    extern __shared__ __half smh[];
    GemmCtx cx;
    gemm_setup(cx, A, W, K, smh);
    float acc[4][4][4];
    ZERO_ACC(acc)
    gemm_main(cx, acc, K);

    EPI_LOOP({
        if (MODE == 2) {
            v0 = fmaxf(v0, 0.f); v0 = v0 * v0;
            v1 = fmaxf(v1, 0.f); v1 = v1 * v1;
            __half2 hv = __floats2half2_rn(v0, v1);
            *(__half2*)((__half*)Cc + off) = hv;
        } else {
            float2 o; o.x = v0; o.y = v1;
            *(float2*)((float*)Cc + off) = o;
        }
    })
}

// Batched TimeMix triple GEMM: z=0 exp(k), z=1 v, z=2 sigmoid(r)
__global__ void __launch_bounds__(256, 2) gemm_tc3(
        const __half* __restrict__ A0, const __half* __restrict__ A1,
        const __half* __restrict__ A2,
        const __half* __restrict__ W0, const __half* __restrict__ W1,
        const __half* __restrict__ W2,
        float* __restrict__ C0, float* __restrict__ C1,
        float* __restrict__ C2, int N, int K) {
    extern __shared__ __half smh[];
    const int z = blockIdx.z;
    const __half* A = (z == 0) ? A0 : (z == 1) ? A1 : A2;
    const __half* W = (z == 0) ? W0 : (z == 1) ? W1 : W2;
    float* Cc       = (z == 0) ? C0 : (z == 1) ? C1 : C2;

    GemmCtx cx;
    gemm_setup(cx, A, W, K, smh);
    float acc[4][4][4];
    ZERO_ACC(acc)
    gemm_main(cx, acc, K);

    EPI_LOOP({
        if (z == 0) {
            v0 = __expf(v0); v1 = __expf(v1);
        } else if (z == 2) {
            v0 = 1.f / (1.f + __expf(-v0));
            v1 = 1.f / (1.f + __expf(-v1));
        }
        float2 o; o.x = v0; o.y = v1;
        *(float2*)(Cc + off) = o;
    })
}

// Fused FFN tail: acc_r = gr@fWr^T (K=1024) -> sigmoid -> packed half;
// acc_kv = kk@fWv^T (K=4096); out = x2 + sigmoid_r * kv.
__global__ void __launch_bounds__(256, 2) gemm_fuse(
        const __half* __restrict__ Ar, const __half* __restrict__ Wr_,
        const __half* __restrict__ Akv, const __half* __restrict__ Wkv,
        const float* __restrict__ x2, float* __restrict__ out) {
    extern __shared__ __half smh[];
    float acc[4][4][4];

    {
        GemmCtx cx;
        gemm_setup(cx, Ar, Wr_, C_, smh);
        ZERO_ACC(acc)
        gemm_main(cx, acc, C_);
    }

    uint32_t rpack[4][4][2];
    #pragma unroll
    for (int mt = 0; mt < 4; ++mt)
        #pragma unroll
        for (int nt = 0; nt < 4; ++nt) {
            float s0 = 1.f / (1.f + __expf(-acc[mt][nt][0]));
            float s1 = 1.f / (1.f + __expf(-acc[mt][nt][1]));
            float s2 = 1.f / (1.f + __expf(-acc[mt][nt][2]));
            float s3 = 1.f / (1.f + __expf(-acc[mt][nt][3]));
            __half2 p0 = __floats2half2_rn(s0, s1);
            __half2 p1 = __floats2half2_rn(s2, s3);
            rpack[mt][nt][0] = *(uint32_t*)&p0;
            rpack[mt][nt][1] = *(uint32_t*)&p1;
        }

    __syncthreads();

    {
        GemmCtx cx;
        gemm_setup(cx, Akv, Wkv, F_, smh);
        ZERO_ACC(acc)
        gemm_main(cx, acc, F_);
    }

    const int N = C_;
    EPI_LOOP({
        float2 a1 = *(const float2*)(x2 + off);
        __half2 hp = *(__half2*)&rpack[mt][nt][hi];
        float2 rr = __half22float2(hp);
        v0 = a1.x + rr.x * v0;
        v1 = a1.y + rr.y * v1;
        float2 o; o.x = v0; o.y = v1;
        *(float2*)(out + off) = o;
    })
}

// ---------------------------------------------------------------------------
// Launch
// ---------------------------------------------------------------------------
template <typename T>
static T* sym(const void* s) {
    void* p = nullptr;
    cudaGetSymbolAddress(&p, s);
    return (T*)p;
}

extern "C" void kernel_launch(void* const* d_in, const int* in_sizes, int n_in,
                              void* d_out, int out_size) {
    const float* x        = (const float*)d_in[0];
    const float* ln1_w    = (const float*)d_in[1];
    const float* ln1_b    = (const float*)d_in[2];
    const float* ln2_w    = (const float*)d_in[3];
    const float* ln2_b    = (const float*)d_in[4];
    const float* t_decay  = (const float*)d_in[5];
    const float* t_first  = (const float*)d_in[6];
    const float* mix_k    = (const float*)d_in[7];
    const float* mix_v    = (const float*)d_in[8];
    const float* mix_r    = (const float*)d_in[9];
    const float* Wk       = (const float*)d_in[10];
    const float* Wv       = (const float*)d_in[11];
    const float* Wr       = (const float*)d_in[12];
    const float* Wo       = (const float*)d_in[13];
    const float* fmix_k   = (const float*)d_in[14];
    const float* fmix_r   = (const float*)d_in[15];
    const float* fWk      = (const float*)d_in[16];   // [F, C]
    const float* fWr      = (const float*)d_in[17];   // [C, C]
    const float* fWv      = (const float*)d_in[18];   // [C, F]
    const float* shortW   = (const float*)d_in[19];
    float* out = (float*)d_out;

    __half* xk   = sym<__half>(g_xk);
    __half* xv   = sym<__half>(g_xv);
    __half* xr   = sym<__half>(g_xr);
    float*  ekb  = sym<float>(g_ek);
    float*  vbuf = sym<float>(g_v);
    float*  rbuf = sym<float>(g_r);
    __half* ao   = sym<__half>(g_ao);
    float*  x2   = sym<float>(g_x2);
    __half* gk   = sym<__half>(g_gk);
    __half* gr   = sym<__half>(g_gr);
    __half* kkb  = sym<__half>(g_kk);
    __half* wkt  = sym<__half>(g_wkt);
    __half* wvt  = sym<__half>(g_wvt);
    __half* wrt  = sym<__half>(g_wrt);
    __half* wos  = sym<__half>(g_wos);
    __half* fwrt = sym<__half>(g_fwrt);
    __half* fwkt = sym<__half>(g_fwkt);
    __half* fwvt = sym<__half>(g_fwvt);

    cudaFuncSetAttribute(gemm_tc<0>, cudaFuncAttributeMaxDynamicSharedMemorySize, GEMM_SMEM);
    cudaFuncSetAttribute(gemm_tc<2>, cudaFuncAttributeMaxDynamicSharedMemorySize, GEMM_SMEM);
    cudaFuncSetAttribute(gemm_tc3, cudaFuncAttributeMaxDynamicSharedMemorySize, GEMM_SMEM);
    cudaFuncSetAttribute(gemm_fuse, cudaFuncAttributeMaxDynamicSharedMemorySize, GEMM_SMEM);

    const dim3 blk(256);
    const dim3 grid_gC(C_ / BN, M_ / BM);        // (8, 128)
    const dim3 grid_gC3(C_ / BN, M_ / BM, 3);    // batched triple
    const dim3 grid_gF(F_ / BN, M_ / BM);        // (32, 128)
    const dim3 grid_lnmix(M_ / ROWS_PB);         // 1024

    // 1: merged C-weight cvt (wk, wv, wr, fWr)
    cvt4C<<<4096, blk>>>(Wk, Wv, Wr, fWr, wkt, wvt, wrt, fwrt);
    // 2: LN1 + mix (+ writes x->half into ao right half)
    ln_mix_kernel<3><<<grid_lnmix, blk>>>(x, ln1_w, ln1_b,
                                          mix_k, mix_v, mix_r, xk, xv, xr, ao);
    // 3: wos pair (Wo | shortW)
    cvt_wos<<<2048, blk>>>(Wo, shortW, wos);
    // 4: TimeMix triple GEMM  <-- ncu capture target
    gemm_tc3<<<grid_gC3, blk, GEMM_SMEM>>>(xk, xv, xr, wkt, wvt, wrt,
                                           ekb, vbuf, rbuf, C_, C_);
    // 5: merged F-weight cvt (fWk, fWv) — needed later only
    cvt2F<<<8192, blk>>>(fWk, fWv, fwkt, fwvt);
    wkv_part<<<(NCHAN * NCH) / 256, blk>>>(t_decay, ekb, vbuf);
    wkv_scan<<<NCHAN / 256, blk>>>(t_decay);
    wkv_out<<<(NCHAN * NCH) / 256, blk>>>(t_decay, t_first, ekb, vbuf, rbuf, ao);
    // x2 = [rwkv | x] @ [Wo | shortW]^T   (K = 2048)
    gemm_tc<0><<<grid_gC, blk, GEMM_SMEM>>>(ao, wos, x2, C_, 2048);

    // --- ChannelMix path ---
    ln_mix_kernel<2><<<grid_lnmix, blk>>>(x2, ln2_w, ln2_b,
                                          fmix_k, fmix_r, nullptr, gk, gr,
                                          nullptr, nullptr);
    gemm_tc<2><<<grid_gF, blk, GEMM_SMEM>>>(gk, fwkt, kkb, F_, C_);
    gemm_fuse<<<grid_gC, blk, GEMM_SMEM>>>(gr, fwrt, kkb, fwvt, x2, out);
}